// round 1
// baseline (speedup 1.0000x reference)
#include <cuda_runtime.h>

// Problem constants
#define N_NODES  1048576
#define N_GRAPHS 4096
#define F_IN     16
#define HID      32

// ---------------------------------------------------------------------------
// Device scratch for folded weights (no allocations allowed).
// A = W_z[0,0][:16,:] + W_z[1,0][:16,:]   (16 x 32)
// C = W_h[0,0][:16,:] + W_h[1,0][:16,:]   (16 x 32)
// ---------------------------------------------------------------------------
__device__ float g_A[512];
__device__ float g_C[512];
__device__ float g_bz[32];
__device__ float g_bh[32];
__device__ float g_wl[32];
__device__ float g_bl;

__global__ void prep_kernel(const float* __restrict__ Wz, const float* __restrict__ bz,
                            const float* __restrict__ Wh, const float* __restrict__ bh,
                            const float* __restrict__ wl, const float* __restrict__ bl) {
    int i = threadIdx.x;                 // 512 threads
    // W shape (2,1,48,32): slice [0,0] at offset 0, slice [1,0] at offset 1536.
    // Rows k<16 (the x-part) are exactly the first 512 elements.
    g_A[i] = Wz[i] + Wz[1536 + i];
    g_C[i] = Wh[i] + Wh[1536 + i];
    if (i < 32) { g_bz[i] = bz[i]; g_bh[i] = bh[i]; g_wl[i] = wl[i]; }
    if (i == 0) g_bl = bl[0];
}

// ---------------------------------------------------------------------------
// Packed fp32x2 helpers (Blackwell-only PTX; ptxas never emits these from C++)
// ---------------------------------------------------------------------------
__device__ __forceinline__ void fma2(unsigned long long& d, unsigned long long a,
                                     unsigned long long b) {
    asm("fma.rn.f32x2 %0, %1, %2, %0;" : "+l"(d) : "l"(a), "l"(b));
}
__device__ __forceinline__ unsigned long long pack2(float v) {
    unsigned long long r;
    asm("mov.b64 %0, {%1, %1};" : "=l"(r) : "f"(v));
    return r;
}
__device__ __forceinline__ void unpack2(unsigned long long v, float& lo, float& hi) {
    asm("mov.b64 {%0, %1}, %2;" : "=f"(lo), "=f"(hi) : "l"(v));
}
__device__ __forceinline__ float tanh_fast(float v) {
    float r;
    asm("tanh.approx.f32 %0, %1;" : "=f"(r) : "f"(v));
    return r;
}

// ---------------------------------------------------------------------------
// Main kernel: 1 block = 1 graph (256 contiguous nodes).
// Lane pairing: lane L (<16) and lane L+16 share nodes {n, n+1}.
//   lane <16 accumulates z = x@A + b_z for both nodes,
//   lane>=16 accumulates t = x@C + b_h for both nodes.
// Each shared-weight LDS.128 then feeds 4 FFMA2 (2 nodes x 2 pairs).
// Epilogue: one shfl.bfly(16) per pair swaps z<->t so each lane finishes
// exactly one node (full MUFU utilization).
// ---------------------------------------------------------------------------
__global__ __launch_bounds__(256, 2)
void rgcn_kernel(const float* __restrict__ x, float* __restrict__ out) {
    // sA at floats [0,512); sC at [528,1040). Byte delta 2112 (== 64 mod 128)
    // puts the two half-warp broadcast addresses on disjoint bank groups.
    __shared__ alignas(128) float sW[1056];
    __shared__ alignas(16) float sbz[32];
    __shared__ alignas(16) float sbh[32];
    __shared__ alignas(16) float swl[32];
    __shared__ float wsum[8];

    const int t = threadIdx.x;

    sW[t]       = g_A[t];
    sW[256 + t] = g_A[256 + t];
    sW[528 + t] = g_C[t];
    sW[784 + t] = g_C[256 + t];
    if (t < 32) { sbz[t] = g_bz[t]; sbh[t] = g_bh[t]; swl[t] = g_wl[t]; }
    __syncthreads();

    const int lane = t & 31;
    const int warp = t >> 5;
    const int pl   = lane & 15;
    const bool isZ = lane < 16;

    const int node0 = (blockIdx.x << 8) + (warp << 5) + (pl << 1);

    // Load x rows for node0, node0+1 (128 contiguous bytes per thread).
    const float4* xp = reinterpret_cast<const float4*>(x) + ((size_t)node0 << 2);
    float4 a0 = xp[0], a1 = xp[1], a2 = xp[2], a3 = xp[3];
    float4 b0 = xp[4], b1 = xp[5], b2 = xp[6], b3 = xp[7];
    float xv0[16] = {a0.x, a0.y, a0.z, a0.w, a1.x, a1.y, a1.z, a1.w,
                     a2.x, a2.y, a2.z, a2.w, a3.x, a3.y, a3.z, a3.w};
    float xv1[16] = {b0.x, b0.y, b0.z, b0.w, b1.x, b1.y, b1.z, b1.w,
                     b2.x, b2.y, b2.z, b2.w, b3.x, b3.y, b3.z, b3.w};

    const float* wbase = isZ ? sW : (sW + 528);
    const unsigned long long* bias =
        reinterpret_cast<const unsigned long long*>(isZ ? sbz : sbh);

    unsigned long long acc0[16], acc1[16];
#pragma unroll
    for (int p = 0; p < 16; p++) { acc0[p] = bias[p]; acc1[p] = bias[p]; }

#pragma unroll
    for (int k = 0; k < 16; k++) {
        const unsigned long long xa = pack2(xv0[k]);
        const unsigned long long xb = pack2(xv1[k]);
        const ulonglong2* row = reinterpret_cast<const ulonglong2*>(wbase + (k << 5));
#pragma unroll
        for (int q = 0; q < 8; q++) {
            ulonglong2 w = row[q];                // LDS.128: 2 output pairs
            fma2(acc0[2 * q],     xa, w.x);
            fma2(acc0[2 * q + 1], xa, w.y);
            fma2(acc1[2 * q],     xb, w.x);
            fma2(acc1[2 * q + 1], xb, w.y);
        }
    }

    // Epilogue: z-lane finishes node0, t-lane finishes node1.
    // z-lane sends acc1 (z of node1) to partner, receives t of node0.
    // t-lane sends acc0 (t of node0) to partner, receives z of node1.
    float s = 0.f;
#pragma unroll
    for (int p = 0; p < 16; p++) {
        unsigned long long sendv = isZ ? acc1[p] : acc0[p];
        unsigned long long recv  = __shfl_xor_sync(0xffffffffu, sendv, 16);
        unsigned long long zp = isZ ? acc0[p] : recv;
        unsigned long long tp = isZ ? recv : acc1[p];

        float z0, z1, t0, t1;
        unpack2(zp, z0, z1);
        unpack2(tp, t0, t1);

        // (1 - sigmoid(z)) = 0.5 - 0.5*tanh(z/2)
        float e0 = fmaf(-0.5f, tanh_fast(0.5f * z0), 0.5f);
        float e1 = fmaf(-0.5f, tanh_fast(0.5f * z1), 0.5f);
        float h0 = tanh_fast(t0);
        float h1 = tanh_fast(t1);
        float r0 = fmaxf(e0 * h0, 0.f);
        float r1 = fmaxf(e1 * h1, 0.f);
        s = fmaf(r0, swl[2 * p],     s);
        s = fmaf(r1, swl[2 * p + 1], s);
    }

    // Block reduction over 256 node scalars (each lane holds one node).
#pragma unroll
    for (int off = 16; off > 0; off >>= 1)
        s += __shfl_xor_sync(0xffffffffu, s, off);
    if (lane == 0) wsum[warp] = s;
    __syncthreads();
    if (t == 0) {
        float tot = 0.f;
#pragma unroll
        for (int i = 0; i < 8; i++) tot += wsum[i];
        out[blockIdx.x] = tot * (1.0f / 256.0f) + g_bl;
    }
}

// ---------------------------------------------------------------------------
// Inputs (metadata order): 0:x 1:edge_index 2:edge_weight 3:batch
//   4:W_z 5:b_z 6:W_r 7:b_r 8:W_h 9:b_h 10:W_lin 11:b_lin
// edge_index/edge_weight/batch/W_r/b_r are mathematically unused (K=1, h0=0,
// batch = repeat(arange(4096),256) by construction).
// ---------------------------------------------------------------------------
extern "C" void kernel_launch(void* const* d_in, const int* in_sizes, int n_in,
                              void* d_out, int out_size) {
    (void)in_sizes; (void)n_in; (void)out_size;
    const float* x  = (const float*)d_in[0];
    const float* Wz = (const float*)d_in[4];
    const float* bz = (const float*)d_in[5];
    const float* Wh = (const float*)d_in[8];
    const float* bh = (const float*)d_in[9];
    const float* wl = (const float*)d_in[10];
    const float* bl = (const float*)d_in[11];
    float* out = (float*)d_out;

    prep_kernel<<<1, 512>>>(Wz, bz, Wh, bh, wl, bl);
    rgcn_kernel<<<N_GRAPHS, 256>>>(x, out);
}

// round 2
// speedup vs baseline: 1.3059x; 1.3059x over previous
#include <cuda_runtime.h>

#define N_GRAPHS 4096
typedef unsigned long long ull;

// ---------------------------------------------------------------------------
// Folded weights (prep kernel writes these; no allocations allowed).
// g_A = 0.5*(W_z[0,0]+W_z[1,0])[:16,:]  stored PASS-MAJOR: [pass][k][j16]
// g_C =      (W_h[0,0]+W_h[1,0])[:16,:] pass-major
// g_bz prescaled by 0.5 (z' = z/2 so sigma(z) = 0.5 + 0.5*tanh(z'))
// ---------------------------------------------------------------------------
__device__ float g_A[512];
__device__ float g_C[512];
__device__ float g_bz[32];
__device__ float g_bh[32];
__device__ float g_wl[32];
__device__ float g_bl;

__global__ void prep_kernel(const float* __restrict__ Wz, const float* __restrict__ bz,
                            const float* __restrict__ Wh, const float* __restrict__ bh,
                            const float* __restrict__ wl, const float* __restrict__ bl) {
    int i = threadIdx.x;                        // 512 threads
    int pass = i >> 8, rem = i & 255;
    int k = rem >> 4, j = rem & 15;
    int src = k * 32 + pass * 16 + j;           // W shape (2,1,48,32); rows k<16 = x-part
    g_A[i] = 0.5f * (Wz[src] + Wz[1536 + src]);
    g_C[i] = Wh[src] + Wh[1536 + src];
    if (i < 32) { g_bz[i] = 0.5f * bz[i]; g_bh[i] = bh[i]; g_wl[i] = wl[i]; }
    if (i == 0) g_bl = bl[0];
}

// ---------------------------------------------------------------------------
// Packed fp32x2 helpers (PTX-only on Blackwell; ptxas never auto-fuses)
// ---------------------------------------------------------------------------
__device__ __forceinline__ void fma2(ull& d, ull a, ull b) {
    asm("fma.rn.f32x2 %0, %1, %2, %0;" : "+l"(d) : "l"(a), "l"(b));
}
__device__ __forceinline__ ull pack2(float v) {
    ull r; asm("mov.b64 %0, {%1, %1};" : "=l"(r) : "f"(v)); return r;
}
__device__ __forceinline__ void unpack2(ull v, float& lo, float& hi) {
    asm("mov.b64 {%0, %1}, %2;" : "=f"(lo), "=f"(hi) : "l"(v));
}
__device__ __forceinline__ float tanh_fast(float v) {
    float r; asm("tanh.approx.f32 %0, %1;" : "=f"(r) : "f"(v)); return r;
}

// ---------------------------------------------------------------------------
// Main kernel: 1 block = 1 graph (256 nodes), 128 threads = 4 warps.
// Warp covers 64 nodes: pl = lane&15 owns nodes {4pl..4pl+3}.
//   lane <16 (z-lane) accumulates z' = 0.5*(x@A+bz) for all 4 nodes,
//   lane>=16 (t-lane) accumulates t  =      x@C+bh  for all 4 nodes.
// Two passes over output halves (16 outputs each) cap acc regs at 32 ull.
// x is loaded ONCE (z-lane loads nodes 0,1; t-lane nodes 2,3) and exchanged
// via shfl.xor(16) — removes the duplicate 64MB of LDG traffic.
// Per-pass epilogue: acc rows exchanged across the half-warp so z-lane
// finishes nodes 0,1 and t-lane nodes 2,3 (balanced MUFU).
// ---------------------------------------------------------------------------
__global__ __launch_bounds__(128, 2)
void rgcn_kernel(const float* __restrict__ x, float* __restrict__ out) {
    // sA at floats [0,512); sC at [528,1040): byte delta 2112 (== 64 mod 128)
    // so the two half-warp broadcast addresses hit disjoint bank halves.
    __shared__ alignas(128) float sW[1040];
    __shared__ alignas(16) float sbz[32];
    __shared__ alignas(16) float sbh[32];
    __shared__ alignas(16) float swl[32];
    __shared__ float wsum[4];

    const int t    = threadIdx.x;
    const int lane = t & 31;
    const int warp = t >> 5;
    const int pl   = lane & 15;
    const bool isZ = lane < 16;

    // ---- issue x loads first (latency overlap with weight staging) ----
    // z-lane loads rows {4pl, 4pl+1}; t-lane rows {4pl+2, 4pl+3}.
    const int row0 = (blockIdx.x << 8) + (warp << 6) + (pl << 2) + (isZ ? 0 : 2);
    const float4* xp = reinterpret_cast<const float4*>(x) + ((size_t)row0 << 2);
    float4 v0 = xp[0], v1 = xp[1], v2 = xp[2], v3 = xp[3];
    float4 v4 = xp[4], v5 = xp[5], v6 = xp[6], v7 = xp[7];

    // ---- stage weights into shared ----
#pragma unroll
    for (int m = 0; m < 4; m++) {
        int i = t + (m << 7);
        sW[i]       = g_A[i];
        sW[528 + i] = g_C[i];
    }
    if (t < 32) { sbz[t] = g_bz[t]; sbh[t] = g_bh[t]; swl[t] = g_wl[t]; }
    __syncthreads();

    // ---- exchange x with partner lane (xor 16): 32 shfl ----
    float own[32] = {v0.x, v0.y, v0.z, v0.w, v1.x, v1.y, v1.z, v1.w,
                     v2.x, v2.y, v2.z, v2.w, v3.x, v3.y, v3.z, v3.w,
                     v4.x, v4.y, v4.z, v4.w, v5.x, v5.y, v5.z, v5.w,
                     v6.x, v6.y, v6.z, v6.w, v7.x, v7.y, v7.z, v7.w};
    float xn0[16], xn1[16], xn2[16], xn3[16];
#pragma unroll
    for (int k = 0; k < 16; k++) {
        float a = own[k], b = own[16 + k];
        float c = __shfl_xor_sync(0xffffffffu, a, 16);
        float d = __shfl_xor_sync(0xffffffffu, b, 16);
        // z-lane: own = nodes 0,1; recv = nodes 2,3.  t-lane: reversed.
        xn0[k] = isZ ? a : c;
        xn1[k] = isZ ? b : d;
        xn2[k] = isZ ? c : a;
        xn3[k] = isZ ? d : b;
    }

    const float* wbase = isZ ? sW : (sW + 528);
    const float* bbase = isZ ? sbz : sbh;

    float s = 0.f;
#pragma unroll
    for (int pass = 0; pass < 2; pass++) {
        const ulonglong2* W = reinterpret_cast<const ulonglong2*>(wbase + (pass << 8));
        const ull* bb = reinterpret_cast<const ull*>(bbase + (pass << 4));

        ull a0[8], a1[8], a2[8], a3[8];
#pragma unroll
        for (int p = 0; p < 8; p++) { ull b = bb[p]; a0[p] = b; a1[p] = b; a2[p] = b; a3[p] = b; }

#pragma unroll
        for (int k = 0; k < 16; k++) {
            ulonglong2 w0 = W[k * 4 + 0];
            ulonglong2 w1 = W[k * 4 + 1];
            ulonglong2 w2 = W[k * 4 + 2];
            ulonglong2 w3 = W[k * 4 + 3];
            ull xa = pack2(xn0[k]);
            fma2(a0[0], xa, w0.x); fma2(a0[1], xa, w0.y);
            fma2(a0[2], xa, w1.x); fma2(a0[3], xa, w1.y);
            fma2(a0[4], xa, w2.x); fma2(a0[5], xa, w2.y);
            fma2(a0[6], xa, w3.x); fma2(a0[7], xa, w3.y);
            ull xb = pack2(xn1[k]);
            fma2(a1[0], xb, w0.x); fma2(a1[1], xb, w0.y);
            fma2(a1[2], xb, w1.x); fma2(a1[3], xb, w1.y);
            fma2(a1[4], xb, w2.x); fma2(a1[5], xb, w2.y);
            fma2(a1[6], xb, w3.x); fma2(a1[7], xb, w3.y);
            ull xc = pack2(xn2[k]);
            fma2(a2[0], xc, w0.x); fma2(a2[1], xc, w0.y);
            fma2(a2[2], xc, w1.x); fma2(a2[3], xc, w1.y);
            fma2(a2[4], xc, w2.x); fma2(a2[5], xc, w2.y);
            fma2(a2[6], xc, w3.x); fma2(a2[7], xc, w3.y);
            ull xd = pack2(xn3[k]);
            fma2(a3[0], xd, w0.x); fma2(a3[1], xd, w0.y);
            fma2(a3[2], xd, w1.x); fma2(a3[3], xd, w1.y);
            fma2(a3[4], xd, w2.x); fma2(a3[5], xd, w2.y);
            fma2(a3[6], xd, w3.x); fma2(a3[7], xd, w3.y);
        }

        // ---- cross-lane z/t pairing + epilogue (16 outputs this pass) ----
        const float* wlp = swl + (pass << 4);
#pragma unroll
        for (int p = 0; p < 8; p++) {
            ull r0 = __shfl_xor_sync(0xffffffffu, a0[p], 16);
            ull r1 = __shfl_xor_sync(0xffffffffu, a1[p], 16);
            ull r2 = __shfl_xor_sync(0xffffffffu, a2[p], 16);
            ull r3 = __shfl_xor_sync(0xffffffffu, a3[p], 16);
            // z-lane finishes nodes 0,1 (z own, t received);
            // t-lane finishes nodes 2,3 (t own, z received).
            ull za = isZ ? a0[p] : r2;
            ull ta = isZ ? r0    : a2[p];
            ull zb = isZ ? a1[p] : r3;
            ull tb = isZ ? r1    : a3[p];

            float wl0 = wlp[2 * p], wl1 = wlp[2 * p + 1];

            float z0, z1, t0, t1;
            unpack2(za, z0, z1); unpack2(ta, t0, t1);
            float e0 = fmaf(-0.5f, tanh_fast(z0), 0.5f);   // 1 - sigmoid(z), z prehalved
            float e1 = fmaf(-0.5f, tanh_fast(z1), 0.5f);
            float h0 = tanh_fast(t0), h1 = tanh_fast(t1);
            float q0 = fmaxf(e0 * h0, 0.f), q1 = fmaxf(e1 * h1, 0.f);
            s = fmaf(q0, wl0, s); s = fmaf(q1, wl1, s);

            unpack2(zb, z0, z1); unpack2(tb, t0, t1);
            e0 = fmaf(-0.5f, tanh_fast(z0), 0.5f);
            e1 = fmaf(-0.5f, tanh_fast(z1), 0.5f);
            h0 = tanh_fast(t0); h1 = tanh_fast(t1);
            q0 = fmaxf(e0 * h0, 0.f); q1 = fmaxf(e1 * h1, 0.f);
            s = fmaf(q0, wl0, s); s = fmaf(q1, wl1, s);
        }
    }

    // ---- reduction: each lane holds sum of 2 nodes; warp = 64 nodes ----
#pragma unroll
    for (int off = 16; off > 0; off >>= 1)
        s += __shfl_xor_sync(0xffffffffu, s, off);
    if (lane == 0) wsum[warp] = s;
    __syncthreads();
    if (t == 0) {
        float tot = (wsum[0] + wsum[1]) + (wsum[2] + wsum[3]);
        out[blockIdx.x] = tot * (1.0f / 256.0f) + g_bl;
    }
}

// ---------------------------------------------------------------------------
// Inputs: 0:x 1:edge_index 2:edge_weight 3:batch 4:W_z 5:b_z 6:W_r 7:b_r
//         8:W_h 9:b_h 10:W_lin 11:b_lin
// edge_index/edge_weight/batch/W_r/b_r mathematically unused (K=1, h0=0,
// batch = repeat(arange(4096),256)).
// ---------------------------------------------------------------------------
extern "C" void kernel_launch(void* const* d_in, const int* in_sizes, int n_in,
                              void* d_out, int out_size) {
    (void)in_sizes; (void)n_in; (void)out_size;
    const float* x  = (const float*)d_in[0];
    const float* Wz = (const float*)d_in[4];
    const float* bz = (const float*)d_in[5];
    const float* Wh = (const float*)d_in[8];
    const float* bh = (const float*)d_in[9];
    const float* wl = (const float*)d_in[10];
    const float* bl = (const float*)d_in[11];
    float* out = (float*)d_out;

    prep_kernel<<<1, 512>>>(Wz, bz, Wh, bh, wl, bl);
    rgcn_kernel<<<N_GRAPHS, 128>>>(x, out);
}

// round 3
// speedup vs baseline: 1.7525x; 1.3421x over previous
#include <cuda_runtime.h>

#define N_GRAPHS 4096
typedef unsigned long long ull;

// ---------------------------------------------------------------------------
// Folded weights, pass-major interleaved layout:
//   g_W[pass][k][s]  (4 x 16 x 16 floats = 1024)
//     s in [0,8):  A(k, 8*pass+s) = 0.5*(W_z[0,0]+W_z[1,0])[k][j]   (prescaled)
//     s in [8,16): C(k, 8*pass+s-8) =    (W_h[0,0]+W_h[1,0])[k][j]
// g_bz prescaled by 0.5 (z' = z/2 so 1-sigmoid(z) = 0.5 - 0.5*tanh(z')).
// ---------------------------------------------------------------------------
__device__ float g_W[1024];
__device__ float g_bz[32];
__device__ float g_bh[32];
__device__ float g_wl[32];
__device__ float g_bl;

__global__ void prep_kernel(const float* __restrict__ Wz, const float* __restrict__ bz,
                            const float* __restrict__ Wh, const float* __restrict__ bh,
                            const float* __restrict__ wl, const float* __restrict__ bl) {
    int i = threadIdx.x;                       // 1024 threads
    int pass = i >> 8;
    int k    = (i >> 4) & 15;
    int s    = i & 15;
    int j    = 8 * pass + (s & 7);
    int src  = k * 32 + j;                     // W shape (2,1,48,32); rows k<16 = x part
    float v;
    if (s < 8) v = 0.5f * (Wz[src] + Wz[1536 + src]);
    else       v = Wh[src] + Wh[1536 + src];
    g_W[i] = v;
    if (i < 32) { g_bz[i] = 0.5f * bz[i]; g_bh[i] = bh[i]; g_wl[i] = wl[i]; }
    if (i == 0) g_bl = bl[0];
}

// ---------------------------------------------------------------------------
// Packed fp32x2 helpers (PTX-only on Blackwell; ptxas never auto-fuses)
// ---------------------------------------------------------------------------
__device__ __forceinline__ void fma2(ull& d, ull a, ull b) {
    asm("fma.rn.f32x2 %0, %1, %2, %0;" : "+l"(d) : "l"(a), "l"(b));
}
__device__ __forceinline__ ull pack2(float v) {
    ull r; asm("mov.b64 %0, {%1, %1};" : "=l"(r) : "f"(v)); return r;
}
__device__ __forceinline__ void unpack2(ull v, float& lo, float& hi) {
    asm("mov.b64 {%0, %1}, %2;" : "=f"(lo), "=f"(hi) : "l"(v));
}
__device__ __forceinline__ float tanh_fast(float v) {
    float r; asm("tanh.approx.f32 %0, %1;" : "=f"(r) : "f"(v)); return r;
}

// ---------------------------------------------------------------------------
// Main kernel: 128 threads/block, each thread owns 4 whole nodes (z AND t).
// Block covers 512 nodes = 2 graphs (warps 0,1 -> graph A; warps 2,3 -> B).
// 4 passes of 8 output columns; per (pass,k) one contiguous, fully
// warp-uniform 64B shared read feeds 32 fma2 (1:8 LDS:FMA ratio).
// No shuffles, no selects, MUFU balanced across all lanes.
// ---------------------------------------------------------------------------
__global__ __launch_bounds__(128, 3)
void rgcn_kernel(const float* __restrict__ x, float* __restrict__ out) {
    __shared__ alignas(128) float sW[1024];
    __shared__ alignas(16) float sbz[32];
    __shared__ alignas(16) float sbh[32];
    __shared__ alignas(16) float swl[32];
    __shared__ float wsum[4];

    const int t    = threadIdx.x;
    const int lane = t & 31;
    const int warp = t >> 5;

    // ---- issue x loads first (4 rows = 256B contiguous per thread) ----
    const int node0 = (blockIdx.x << 9) + (t << 2);
    const float4* xp = reinterpret_cast<const float4*>(x) + ((size_t)node0 << 2);
    float4 r0 = xp[0],  r1 = xp[1],  r2 = xp[2],  r3 = xp[3];
    float4 r4 = xp[4],  r5 = xp[5],  r6 = xp[6],  r7 = xp[7];
    float4 r8 = xp[8],  r9 = xp[9],  rA = xp[10], rB = xp[11];
    float4 rC = xp[12], rD = xp[13], rE = xp[14], rF = xp[15];

    // ---- stage weights into shared ----
#pragma unroll
    for (int m = 0; m < 8; m++) {
        int i = t + (m << 7);
        sW[i] = g_W[i];
    }
    if (t < 32) { sbz[t] = g_bz[t]; sbh[t] = g_bh[t]; swl[t] = g_wl[t]; }
    __syncthreads();

    float xv[4][16] = {
        {r0.x, r0.y, r0.z, r0.w, r1.x, r1.y, r1.z, r1.w,
         r2.x, r2.y, r2.z, r2.w, r3.x, r3.y, r3.z, r3.w},
        {r4.x, r4.y, r4.z, r4.w, r5.x, r5.y, r5.z, r5.w,
         r6.x, r6.y, r6.z, r6.w, r7.x, r7.y, r7.z, r7.w},
        {r8.x, r8.y, r8.z, r8.w, r9.x, r9.y, r9.z, r9.w,
         rA.x, rA.y, rA.z, rA.w, rB.x, rB.y, rB.z, rB.w},
        {rC.x, rC.y, rC.z, rC.w, rD.x, rD.y, rD.z, rD.w,
         rE.x, rE.y, rE.z, rE.w, rF.x, rF.y, rF.z, rF.w}};

    float s = 0.f;
#pragma unroll
    for (int pass = 0; pass < 4; pass++) {
        const ulonglong2* W = reinterpret_cast<const ulonglong2*>(sW + (pass << 8));
        const ull* bzp = reinterpret_cast<const ull*>(sbz) + (pass << 2);
        const ull* bhp = reinterpret_cast<const ull*>(sbh) + (pass << 2);

        ull az[4][4], at[4][4];
#pragma unroll
        for (int q = 0; q < 4; q++) {
            ull bz2 = bzp[q], bh2 = bhp[q];
#pragma unroll
            for (int n = 0; n < 4; n++) { az[n][q] = bz2; at[n][q] = bh2; }
        }

#pragma unroll
        for (int k = 0; k < 16; k++) {
            // one uniform 64B row: A pairs (wa0,wa1), C pairs (wc0,wc1)
            ulonglong2 wa0 = W[k * 4 + 0];
            ulonglong2 wa1 = W[k * 4 + 1];
            ulonglong2 wc0 = W[k * 4 + 2];
            ulonglong2 wc1 = W[k * 4 + 3];
#pragma unroll
            for (int n = 0; n < 4; n++) {
                ull xk = pack2(xv[n][k]);
                fma2(az[n][0], xk, wa0.x); fma2(az[n][1], xk, wa0.y);
                fma2(az[n][2], xk, wa1.x); fma2(az[n][3], xk, wa1.y);
                fma2(at[n][0], xk, wc0.x); fma2(at[n][1], xk, wc0.y);
                fma2(at[n][2], xk, wc1.x); fma2(at[n][3], xk, wc1.y);
            }
        }

        // ---- epilogue for this pass: 8 output columns x 4 nodes ----
        const float* wlp = swl + (pass << 3);
#pragma unroll
        for (int q = 0; q < 4; q++) {
            float wl0 = wlp[2 * q], wl1 = wlp[2 * q + 1];
#pragma unroll
            for (int n = 0; n < 4; n++) {
                float z0, z1, t0, t1;
                unpack2(az[n][q], z0, z1);
                unpack2(at[n][q], t0, t1);
                float e0 = fmaf(-0.5f, tanh_fast(z0), 0.5f);  // 1 - sigmoid(z)
                float e1 = fmaf(-0.5f, tanh_fast(z1), 0.5f);
                float h0 = tanh_fast(t0);
                float h1 = tanh_fast(t1);
                float q0 = fmaxf(e0 * h0, 0.f);
                float q1 = fmaxf(e1 * h1, 0.f);
                s = fmaf(q0, wl0, s);
                s = fmaf(q1, wl1, s);
            }
        }
    }

    // ---- reduction: warp = 128 nodes; warps {0,1} graph A, {2,3} graph B ----
#pragma unroll
    for (int off = 16; off > 0; off >>= 1)
        s += __shfl_xor_sync(0xffffffffu, s, off);
    if (lane == 0) wsum[warp] = s;
    __syncthreads();
    if (t < 2) {
        float tot = wsum[2 * t] + wsum[2 * t + 1];
        out[2 * blockIdx.x + t] = tot * (1.0f / 256.0f) + g_bl;
    }
}

// ---------------------------------------------------------------------------
// Inputs: 0:x 1:edge_index 2:edge_weight 3:batch 4:W_z 5:b_z 6:W_r 7:b_r
//         8:W_h 9:b_h 10:W_lin 11:b_lin
// edge_index/edge_weight/batch/W_r/b_r mathematically unused (K=1, h0=0,
// batch = repeat(arange(4096),256)).
// ---------------------------------------------------------------------------
extern "C" void kernel_launch(void* const* d_in, const int* in_sizes, int n_in,
                              void* d_out, int out_size) {
    (void)in_sizes; (void)n_in; (void)out_size;
    const float* x  = (const float*)d_in[0];
    const float* Wz = (const float*)d_in[4];
    const float* bz = (const float*)d_in[5];
    const float* Wh = (const float*)d_in[8];
    const float* bh = (const float*)d_in[9];
    const float* wl = (const float*)d_in[10];
    const float* bl = (const float*)d_in[11];
    float* out = (float*)d_out;

    prep_kernel<<<1, 1024>>>(Wz, bz, Wh, bh, wl, bl);
    rgcn_kernel<<<N_GRAPHS / 2, 128>>>(x, out);
}

// round 5
// speedup vs baseline: 2.8098x; 1.6033x over previous
#include <cuda_runtime.h>
#include <cuda_bf16.h>
#include <cstdint>

#define N_GRAPHS 4096

// ---------------------------------------------------------------------------
// g_Bfrag: folded weights in the EXACT mma.m16n8k16 B-fragment lane layout.
//   index = ((v*8 + nt)*2 + r)*32 + lane
//   v: 0 = bf16 hi part, 1 = bf16 lo residual
//   nt: n-tile 0..7 (cols 8nt..8nt+7 of combined W[16 x 64])
//   r: fragment register 0..1 (k rows +0 / +8)
//   lane: b0 = W[2*(lane%4)+8r ][8nt + lane/4] (low half)
//         b1 = W[2*(lane%4)+8r+1][...]          (high half)
// Combined W cols: n<32 -> 0.5*(W_z[0,0]+W_z[1,0])[k][n]  (z path, prescaled)
//                  n>=32 ->     (W_h[0,0]+W_h[1,0])[k][n-32] (t path)
// g_bz prescaled by 0.5 (z' = z/2 so 1-sigmoid(z) = 0.5 - 0.5*tanh(z')).
// ---------------------------------------------------------------------------
__device__ uint32_t g_Bfrag[1024];
__device__ float g_bz[32];
__device__ float g_bh[32];
__device__ float g_wl[32];
__device__ float g_bl;

__global__ void prep_kernel(const float* __restrict__ Wz, const float* __restrict__ bz,
                            const float* __restrict__ Wh, const float* __restrict__ bh,
                            const float* __restrict__ wl, const float* __restrict__ bl) {
    int i = threadIdx.x;                   // 1024 threads
    int v  = i >> 9;
    int nt = (i >> 6) & 7;
    int r  = (i >> 5) & 1;
    int l  = i & 31;
    int n  = nt * 8 + (l >> 2);
    int k  = ((l & 3) << 1) + (r << 3);
    float w0, w1;
    if (n < 32) {                          // W shape (2,1,48,32); rows k<16 = x part
        w0 = 0.5f * (Wz[k * 32 + n] + Wz[1536 + k * 32 + n]);
        w1 = 0.5f * (Wz[(k + 1) * 32 + n] + Wz[1536 + (k + 1) * 32 + n]);
    } else {
        int nn = n - 32;
        w0 = Wh[k * 32 + nn] + Wh[1536 + k * 32 + nn];
        w1 = Wh[(k + 1) * 32 + nn] + Wh[1536 + (k + 1) * 32 + nn];
    }
    if (v == 1) {                          // lo residual
        w0 -= __bfloat162float(__float2bfloat16(w0));
        w1 -= __bfloat162float(__float2bfloat16(w1));
    }
    __nv_bfloat162 p = __floats2bfloat162_rn(w0, w1);   // x = w0 (low half)
    g_Bfrag[i] = *reinterpret_cast<uint32_t*>(&p);
    if (i < 32) { g_bz[i] = 0.5f * bz[i]; g_bh[i] = bh[i]; g_wl[i] = wl[i]; }
    if (i == 0) g_bl = bl[0];
}

// ---------------------------------------------------------------------------
// Baseline-ISA helpers (compile for plain sm_103 — no arch-accelerated feats)
// ---------------------------------------------------------------------------
__device__ __forceinline__ uint32_t smem_u32(const void* p) {
    uint32_t a;
    asm("{ .reg .u64 t; cvta.to.shared.u64 t, %1; cvt.u32.u64 %0, t; }" : "=r"(a) : "l"(p));
    return a;
}
__device__ __forceinline__ float tanh_fast(float v) {
    float r; asm("tanh.approx.f32 %0, %1;" : "=f"(r) : "f"(v)); return r;
}
__device__ __forceinline__ uint32_t cvt_bf16x2(float lo, float hi) {
    uint32_t r;  // packs: low half = lo, high half = hi
    asm("cvt.rn.bf16x2.f32 %0, %1, %2;" : "=r"(r) : "f"(hi), "f"(lo));
    return r;
}
__device__ __forceinline__ void ldmatrix_x4(uint32_t* a, uint32_t addr) {
    asm volatile("ldmatrix.sync.aligned.m8n8.x4.shared.b16 {%0,%1,%2,%3}, [%4];"
                 : "=r"(a[0]), "=r"(a[1]), "=r"(a[2]), "=r"(a[3]) : "r"(addr));
}
__device__ __forceinline__ void mma_bf16(float* d, const uint32_t* a, uint32_t b0, uint32_t b1) {
    asm volatile(
        "mma.sync.aligned.m16n8k16.row.col.f32.bf16.bf16.f32 "
        "{%0,%1,%2,%3}, {%4,%5,%6,%7}, {%8,%9}, {%0,%1,%2,%3};"
        : "+f"(d[0]), "+f"(d[1]), "+f"(d[2]), "+f"(d[3])
        : "r"(a[0]), "r"(a[1]), "r"(a[2]), "r"(a[3]), "r"(b0), "r"(b1));
}

// ---------------------------------------------------------------------------
// SMEM: xs[256 rows x 80B] = 20480 (bf16 x staging: bytes [0,32)=hi k0..15,
//       [32,64)=lo; 80B pitch -> rows mod 128 all distinct 16B groups:
//       conflict-free STS.128 and ldmatrix)
//       20480: bz(128)  20608: bh(128)  20736: wl(128)  20864: wsum(32)
// ---------------------------------------------------------------------------
#define PITCH   80
#define OFF_BZ  20480
#define OFF_BH  20608
#define OFF_WL  20736
#define OFF_WS  20864
#define SMEM_SZ 20896

__global__ __launch_bounds__(256, 2)
void rgcn_kernel(const float* __restrict__ x, float* __restrict__ out) {
    extern __shared__ char smem[];
    const uint32_t xsb = smem_u32(smem);
    const int t    = threadIdx.x;
    const int lane = t & 31;
    const int wid  = t >> 5;

    // ---- load x row (1 node/thread, 64B coalesced), bf16 hi/lo split ----
    const int node = (blockIdx.x << 8) + t;
    const float4* xp = reinterpret_cast<const float4*>(x) + ((size_t)node << 2);
    float4 v0 = xp[0], v1 = xp[1], v2 = xp[2], v3 = xp[3];
    float v[16] = {v0.x, v0.y, v0.z, v0.w, v1.x, v1.y, v1.z, v1.w,
                   v2.x, v2.y, v2.z, v2.w, v3.x, v3.y, v3.z, v3.w};
    uint32_t hi[8], lo[8];
#pragma unroll
    for (int p = 0; p < 8; p++) {
        float a = v[2 * p], b = v[2 * p + 1];
        uint32_t h = cvt_bf16x2(a, b);
        float af = __uint_as_float(h << 16);
        float bf = __uint_as_float(h & 0xffff0000u);
        hi[p] = h;
        lo[p] = cvt_bf16x2(a - af, b - bf);
    }
    {
        uint4* row = reinterpret_cast<uint4*>(smem + t * PITCH);
        row[0] = make_uint4(hi[0], hi[1], hi[2], hi[3]);
        row[1] = make_uint4(hi[4], hi[5], hi[6], hi[7]);
        row[2] = make_uint4(lo[0], lo[1], lo[2], lo[3]);
        row[3] = make_uint4(lo[4], lo[5], lo[6], lo[7]);
    }
    if (t < 32) {
        reinterpret_cast<float*>(smem + OFF_BZ)[t] = g_bz[t];
        reinterpret_cast<float*>(smem + OFF_BH)[t] = g_bh[t];
        reinterpret_cast<float*>(smem + OFF_WL)[t] = g_wl[t];
    }

    // ---- B fragments (uniform across warps; coalesced 4B/lane LDG) ----
    uint32_t Bh[8][2], Bl[8][2];
#pragma unroll
    for (int nt = 0; nt < 8; nt++) {
#pragma unroll
        for (int r = 0; r < 2; r++) {
            Bh[nt][r] = g_Bfrag[nt * 64 + r * 32 + lane];
            Bl[nt][r] = g_Bfrag[512 + nt * 64 + r * 32 + lane];
        }
    }
    __syncthreads();

    const float* sbz = reinterpret_cast<const float*>(smem + OFF_BZ);
    const float* sbh = reinterpret_cast<const float*>(smem + OFF_BH);
    const float* swl = reinterpret_cast<const float*>(smem + OFF_WL);

    float s = 0.f;
#pragma unroll
    for (int m = 0; m < 2; m++) {
        // ---- A fragments via ldmatrix.x4 (rows = nodes, cols = k) ----
        const int rowbase = (wid << 5) + (m << 4);
        const uint32_t aaddr = xsb + (rowbase + (lane & 15)) * PITCH + ((lane >> 4) << 4);
        uint32_t Ah[4], Al[4];
        ldmatrix_x4(Ah, aaddr);
        ldmatrix_x4(Al, aaddr + 32);

        float D[8][4];
#pragma unroll
        for (int nt = 0; nt < 8; nt++) {
            D[nt][0] = 0.f; D[nt][1] = 0.f; D[nt][2] = 0.f; D[nt][3] = 0.f;
            mma_bf16(D[nt], Ah, Bh[nt][0], Bh[nt][1]);
            mma_bf16(D[nt], Al, Bh[nt][0], Bh[nt][1]);
            mma_bf16(D[nt], Ah, Bl[nt][0], Bl[nt][1]);
        }

        // ---- epilogue: z in n-tiles 0..3, matching t in n-tiles 4..7 ----
        const int c0 = (lane & 3) << 1;
#pragma unroll
        for (int nt = 0; nt < 4; nt++) {
            float2 bz2 = *reinterpret_cast<const float2*>(sbz + 8 * nt + c0);
            float2 bh2 = *reinterpret_cast<const float2*>(sbh + 8 * nt + c0);
            float2 wl2 = *reinterpret_cast<const float2*>(swl + 8 * nt + c0);
#pragma unroll
            for (int i = 0; i < 4; i++) {
                float zb = (i & 1) ? bz2.y : bz2.x;
                float hb = (i & 1) ? bh2.y : bh2.x;
                float wv = (i & 1) ? wl2.y : wl2.x;
                float z  = D[nt][i] + zb;          // already pre-halved
                float tt = D[nt + 4][i] + hb;
                float e = fmaf(-0.5f, tanh_fast(z), 0.5f);   // 1 - sigmoid
                float h = tanh_fast(tt);
                s = fmaf(fmaxf(e * h, 0.f), wv, s);
            }
        }
    }

    // ---- block reduction over the graph's 256 nodes ----
#pragma unroll
    for (int off = 16; off > 0; off >>= 1)
        s += __shfl_xor_sync(0xffffffffu, s, off);
    float* wsum = reinterpret_cast<float*>(smem + OFF_WS);
    if (lane == 0) wsum[wid] = s;
    __syncthreads();
    if (t == 0) {
        float tot = ((wsum[0] + wsum[1]) + (wsum[2] + wsum[3])) +
                    ((wsum[4] + wsum[5]) + (wsum[6] + wsum[7]));
        out[blockIdx.x] = tot * (1.0f / 256.0f) + g_bl;
    }
}

// ---------------------------------------------------------------------------
// Inputs: 0:x 1:edge_index 2:edge_weight 3:batch 4:W_z 5:b_z 6:W_r 7:b_r
//         8:W_h 9:b_h 10:W_lin 11:b_lin
// edge_index/edge_weight/batch/W_r/b_r mathematically unused (K=1, h0=0,
// batch = repeat(arange(4096),256)).
// ---------------------------------------------------------------------------
extern "C" void kernel_launch(void* const* d_in, const int* in_sizes, int n_in,
                              void* d_out, int out_size) {
    (void)in_sizes; (void)n_in; (void)out_size;
    const float* x  = (const float*)d_in[0];
    const float* Wz = (const float*)d_in[4];
    const float* bz = (const float*)d_in[5];
    const float* Wh = (const float*)d_in[8];
    const float* bh = (const float*)d_in[9];
    const float* wl = (const float*)d_in[10];
    const float* bl = (const float*)d_in[11];
    float* out = (float*)d_out;

    prep_kernel<<<1, 1024>>>(Wz, bz, Wh, bh, wl, bl);
    rgcn_kernel<<<N_GRAPHS, 256, SMEM_SZ>>>(x, out);
}

// round 6
// speedup vs baseline: 3.1559x; 1.1232x over previous
#include <cuda_runtime.h>
#include <cuda_bf16.h>
#include <cstdint>

#define N_GRAPHS 4096

// ---------------------------------------------------------------------------
// g_Bfrag: folded weights in mma.m16n8k16 B-fragment lane layout, regs paired
// for 64-bit loads:  index = (((v*8 + nt)*32) + lane)*2 + r
//   v: 0 = bf16 hi part, 1 = bf16 lo residual
//   nt: n-tile 0..7 (cols 8nt..8nt+7 of combined W[16 x 64])
//   r: fragment register 0..1 (k rows +0 / +8)
//   lane: b(r) packs W[2*(lane%4)+8r][8nt+lane/4] (lo half) and
//                 W[2*(lane%4)+8r+1][...] (hi half)
// Combined W cols: n<32 -> 0.5*(W_z[0,0]+W_z[1,0])[k][n]  (z path, prescaled)
//                  n>=32 ->     (W_h[0,0]+W_h[1,0])[k][n-32] (t path)
// g_bz prescaled by 0.5 (z' = z/2 so 1-sigmoid(z) = 0.5 - 0.5*tanh(z')).
// ---------------------------------------------------------------------------
__device__ uint32_t g_Bfrag[1024];
__device__ float g_bz[32];
__device__ float g_bh[32];
__device__ float g_wl[32];
__device__ float g_bl;

__global__ void prep_kernel(const float* __restrict__ Wz, const float* __restrict__ bz,
                            const float* __restrict__ Wh, const float* __restrict__ bh,
                            const float* __restrict__ wl, const float* __restrict__ bl) {
    int i = threadIdx.x;                   // 1024 threads
    int r  = i & 1;
    int l  = (i >> 1) & 31;
    int nt = (i >> 6) & 7;
    int v  = i >> 9;
    int n  = nt * 8 + (l >> 2);
    int k  = ((l & 3) << 1) + (r << 3);
    float w0, w1;
    if (n < 32) {                          // W shape (2,1,48,32); rows k<16 = x part
        w0 = 0.5f * (Wz[k * 32 + n] + Wz[1536 + k * 32 + n]);
        w1 = 0.5f * (Wz[(k + 1) * 32 + n] + Wz[1536 + (k + 1) * 32 + n]);
    } else {
        int nn = n - 32;
        w0 = Wh[k * 32 + nn] + Wh[1536 + k * 32 + nn];
        w1 = Wh[(k + 1) * 32 + nn] + Wh[1536 + (k + 1) * 32 + nn];
    }
    if (v == 1) {                          // lo residual
        w0 -= __bfloat162float(__float2bfloat16(w0));
        w1 -= __bfloat162float(__float2bfloat16(w1));
    }
    __nv_bfloat162 p = __floats2bfloat162_rn(w0, w1);   // low half = w0
    g_Bfrag[i] = *reinterpret_cast<uint32_t*>(&p);
    if (i < 32) { g_bz[i] = 0.5f * bz[i]; g_bh[i] = bh[i]; g_wl[i] = wl[i]; }
    if (i == 0) g_bl = bl[0];
}

// ---------------------------------------------------------------------------
// Baseline-ISA helpers (compile for plain sm_103 — no arch-accelerated feats)
// ---------------------------------------------------------------------------
__device__ __forceinline__ uint32_t smem_u32(const void* p) {
    uint32_t a;
    asm("{ .reg .u64 t; cvta.to.shared.u64 t, %1; cvt.u32.u64 %0, t; }" : "=r"(a) : "l"(p));
    return a;
}
__device__ __forceinline__ float tanh_fast(float v) {
    float r; asm("tanh.approx.f32 %0, %1;" : "=f"(r) : "f"(v)); return r;
}
__device__ __forceinline__ uint32_t cvt_bf16x2(float lo, float hi) {
    uint32_t r;  // packs: low half = lo, high half = hi
    asm("cvt.rn.bf16x2.f32 %0, %1, %2;" : "=r"(r) : "f"(hi), "f"(lo));
    return r;
}
__device__ __forceinline__ void ldmatrix_x4(uint32_t* a, uint32_t addr) {
    asm volatile("ldmatrix.sync.aligned.m8n8.x4.shared.b16 {%0,%1,%2,%3}, [%4];"
                 : "=r"(a[0]), "=r"(a[1]), "=r"(a[2]), "=r"(a[3]) : "r"(addr));
}
__device__ __forceinline__ void mma_bf16(float* d, const uint32_t* a, uint32_t b0, uint32_t b1) {
    asm volatile(
        "mma.sync.aligned.m16n8k16.row.col.f32.bf16.bf16.f32 "
        "{%0,%1,%2,%3}, {%4,%5,%6,%7}, {%8,%9}, {%0,%1,%2,%3};"
        : "+f"(d[0]), "+f"(d[1]), "+f"(d[2]), "+f"(d[3])
        : "r"(a[0]), "r"(a[1]), "r"(a[2]), "r"(a[3]), "r"(b0), "r"(b1));
}
__device__ __forceinline__ uint2 lds_v2(uint32_t addr) {
    uint2 v;
    asm volatile("ld.shared.v2.b32 {%0, %1}, [%2];" : "=r"(v.x), "=r"(v.y) : "r"(addr));
    return v;
}

// ---------------------------------------------------------------------------
// SMEM: xs[256 rows x 80B] = 20480 (bf16 x staging: bytes [0,32)=hi k0..15,
//       [32,64)=lo; 80B pitch -> rows mod 128 all distinct 16B groups:
//       conflict-free STS.128 and ldmatrix)
//       20480: Bfrag(4096)  24576: bz(128)  24704: bh(128)  24832: wl(128)
//       24960: wsum(32)
// ---------------------------------------------------------------------------
#define PITCH   80
#define OFF_B   20480
#define OFF_BZ  24576
#define OFF_BH  24704
#define OFF_WL  24832
#define OFF_WS  24960
#define SMEM_SZ 24992

__global__ __launch_bounds__(256, 3)
void rgcn_kernel(const float* __restrict__ x, float* __restrict__ out) {
    extern __shared__ char smem[];
    const uint32_t sb = smem_u32(smem);
    const int t    = threadIdx.x;
    const int lane = t & 31;
    const int wid  = t >> 5;

    // ---- load x row (1 node/thread, 64B coalesced) ----
    const int node = (blockIdx.x << 8) + t;
    const float4* xp = reinterpret_cast<const float4*>(x) + ((size_t)node << 2);
    float4 v0 = xp[0], v1 = xp[1], v2 = xp[2], v3 = xp[3];

    // ---- stage B fragments (4KB) + biases into shared ----
    reinterpret_cast<uint4*>(smem + OFF_B)[t] =
        reinterpret_cast<const uint4*>(g_Bfrag)[t];
    if (t < 32) {
        reinterpret_cast<float*>(smem + OFF_BZ)[t] = g_bz[t];
        reinterpret_cast<float*>(smem + OFF_BH)[t] = g_bh[t];
        reinterpret_cast<float*>(smem + OFF_WL)[t] = g_wl[t];
    }

    // ---- bf16 hi/lo split of x, STS into staging ----
    {
        float v[16] = {v0.x, v0.y, v0.z, v0.w, v1.x, v1.y, v1.z, v1.w,
                       v2.x, v2.y, v2.z, v2.w, v3.x, v3.y, v3.z, v3.w};
        uint32_t hi[8], lo[8];
#pragma unroll
        for (int p = 0; p < 8; p++) {
            float a = v[2 * p], b = v[2 * p + 1];
            uint32_t h = cvt_bf16x2(a, b);
            float af = __uint_as_float(h << 16);
            float bf = __uint_as_float(h & 0xffff0000u);
            hi[p] = h;
            lo[p] = cvt_bf16x2(a - af, b - bf);
        }
        uint4* row = reinterpret_cast<uint4*>(smem + t * PITCH);
        row[0] = make_uint4(hi[0], hi[1], hi[2], hi[3]);
        row[1] = make_uint4(hi[4], hi[5], hi[6], hi[7]);
        row[2] = make_uint4(lo[0], lo[1], lo[2], lo[3]);
        row[3] = make_uint4(lo[4], lo[5], lo[6], lo[7]);
    }
    __syncthreads();

    const float* sbz = reinterpret_cast<const float*>(smem + OFF_BZ);
    const float* sbh = reinterpret_cast<const float*>(smem + OFF_BH);
    const float* swl = reinterpret_cast<const float*>(smem + OFF_WL);
    const uint32_t bfb = sb + OFF_B + lane * 8;   // per-lane B-frag base
    const int c0 = (lane & 3) << 1;

    float s = 0.f;
#pragma unroll
    for (int m = 0; m < 2; m++) {
        // ---- A fragments via ldmatrix.x4 (rows = nodes, cols = k) ----
        const int rowbase = (wid << 5) + (m << 4);
        const uint32_t aaddr = sb + (rowbase + (lane & 15)) * PITCH + ((lane >> 4) << 4);
        uint32_t Ah[4], Al[4];
        ldmatrix_x4(Ah, aaddr);
        ldmatrix_x4(Al, aaddr + 32);

        // ---- stream (z,t) column-pairs: p pairs n-tiles p (z) and p+4 (t) ----
#pragma unroll
        for (int p = 0; p < 4; p++) {
            // B fragments: (v,nt) at offset ((v*8+nt)*32)*8 from per-lane base
            uint2 Bzh = lds_v2(bfb + (p)     * 256);
            uint2 Bth = lds_v2(bfb + (p + 4) * 256);
            uint2 Bzl = lds_v2(bfb + (p + 8) * 256);
            uint2 Btl = lds_v2(bfb + (p + 12) * 256);

            float Dz[4] = {0.f, 0.f, 0.f, 0.f};
            float Dt[4] = {0.f, 0.f, 0.f, 0.f};
            mma_bf16(Dz, Ah, Bzh.x, Bzh.y);
            mma_bf16(Dt, Ah, Bth.x, Bth.y);
            mma_bf16(Dz, Al, Bzh.x, Bzh.y);
            mma_bf16(Dt, Al, Bth.x, Bth.y);
            mma_bf16(Dz, Ah, Bzl.x, Bzl.y);
            mma_bf16(Dt, Ah, Btl.x, Btl.y);

            float2 bz2 = *reinterpret_cast<const float2*>(sbz + 8 * p + c0);
            float2 bh2 = *reinterpret_cast<const float2*>(sbh + 8 * p + c0);
            float2 wl2 = *reinterpret_cast<const float2*>(swl + 8 * p + c0);
#pragma unroll
            for (int i = 0; i < 4; i++) {
                float zb = (i & 1) ? bz2.y : bz2.x;
                float hb = (i & 1) ? bh2.y : bh2.x;
                float wv = (i & 1) ? wl2.y : wl2.x;
                float z  = Dz[i] + zb;                       // already pre-halved
                float tt = Dt[i] + hb;
                float e = fmaf(-0.5f, tanh_fast(z), 0.5f);   // 1 - sigmoid
                float h = tanh_fast(tt);
                s = fmaf(fmaxf(e * h, 0.f), wv, s);
            }
        }
    }

    // ---- block reduction over the graph's 256 nodes ----
#pragma unroll
    for (int off = 16; off > 0; off >>= 1)
        s += __shfl_xor_sync(0xffffffffu, s, off);
    float* wsum = reinterpret_cast<float*>(smem + OFF_WS);
    if (lane == 0) wsum[wid] = s;
    __syncthreads();
    if (t == 0) {
        float tot = ((wsum[0] + wsum[1]) + (wsum[2] + wsum[3])) +
                    ((wsum[4] + wsum[5]) + (wsum[6] + wsum[7]));
        out[blockIdx.x] = tot * (1.0f / 256.0f) + g_bl;
    }
}

// ---------------------------------------------------------------------------
// Inputs: 0:x 1:edge_index 2:edge_weight 3:batch 4:W_z 5:b_z 6:W_r 7:b_r
//         8:W_h 9:b_h 10:W_lin 11:b_lin
// edge_index/edge_weight/batch/W_r/b_r mathematically unused (K=1, h0=0,
// batch = repeat(arange(4096),256)).
// ---------------------------------------------------------------------------
extern "C" void kernel_launch(void* const* d_in, const int* in_sizes, int n_in,
                              void* d_out, int out_size) {
    (void)in_sizes; (void)n_in; (void)out_size;
    const float* x  = (const float*)d_in[0];
    const float* Wz = (const float*)d_in[4];
    const float* bz = (const float*)d_in[5];
    const float* Wh = (const float*)d_in[8];
    const float* bh = (const float*)d_in[9];
    const float* wl = (const float*)d_in[10];
    const float* bl = (const float*)d_in[11];
    float* out = (float*)d_out;

    prep_kernel<<<1, 1024>>>(Wz, bz, Wh, bh, wl, bl);
    rgcn_kernel<<<N_GRAPHS, 256, SMEM_SZ>>>(x, out);
}

// round 7
// speedup vs baseline: 3.3323x; 1.0559x over previous
#include <cuda_runtime.h>
#include <cuda_bf16.h>
#include <cstdint>

#define N_GRAPHS 4096

// ---------------------------------------------------------------------------
// g_Bfrag: folded weights in mma.m16n8k16 B-fragment lane layout, regs paired
// for 64-bit loads:  index = (((v*8 + nt)*32) + lane)*2 + r
//   v: 0 = bf16 hi part, 1 = bf16 lo residual
//   nt: n-tile 0..7 (cols 8nt..8nt+7 of combined W[16 x 64])
//   r: fragment register 0..1 (k rows +0 / +8)
//   lane: b(r) packs W[2*(lane%4)+8r][8nt+lane/4] (lo half) and
//                 W[2*(lane%4)+8r+1][...] (hi half)
// Combined W cols: n<32 -> 0.5*(W_z[0,0]+W_z[1,0])[k][n]  (z path, prescaled)
//                  n>=32 ->     (W_h[0,0]+W_h[1,0])[k][n-32] (t path)
// g_bz prescaled by 0.5 (z' = z/2 so 1-sigmoid(z) = 0.5 - 0.5*tanh(z')).
// ---------------------------------------------------------------------------
__device__ uint32_t g_Bfrag[1024];
__device__ float g_bz[32];
__device__ float g_bh[32];
__device__ float g_wl[32];
__device__ float g_bl;

__global__ void prep_kernel(const float* __restrict__ Wz, const float* __restrict__ bz,
                            const float* __restrict__ Wh, const float* __restrict__ bh,
                            const float* __restrict__ wl, const float* __restrict__ bl) {
    int i = threadIdx.x;                   // 1024 threads
    int r  = i & 1;
    int l  = (i >> 1) & 31;
    int nt = (i >> 6) & 7;
    int v  = i >> 9;
    int n  = nt * 8 + (l >> 2);
    int k  = ((l & 3) << 1) + (r << 3);
    float w0, w1;
    if (n < 32) {                          // W shape (2,1,48,32); rows k<16 = x part
        w0 = 0.5f * (Wz[k * 32 + n] + Wz[1536 + k * 32 + n]);
        w1 = 0.5f * (Wz[(k + 1) * 32 + n] + Wz[1536 + (k + 1) * 32 + n]);
    } else {
        int nn = n - 32;
        w0 = Wh[k * 32 + nn] + Wh[1536 + k * 32 + nn];
        w1 = Wh[(k + 1) * 32 + nn] + Wh[1536 + (k + 1) * 32 + nn];
    }
    if (v == 1) {                          // lo residual
        w0 -= __bfloat162float(__float2bfloat16(w0));
        w1 -= __bfloat162float(__float2bfloat16(w1));
    }
    __nv_bfloat162 p = __floats2bfloat162_rn(w0, w1);   // low half = w0
    g_Bfrag[i] = *reinterpret_cast<uint32_t*>(&p);
    if (i < 32) { g_bz[i] = 0.5f * bz[i]; g_bh[i] = bh[i]; g_wl[i] = wl[i]; }
    if (i == 0) g_bl = bl[0];
}

// ---------------------------------------------------------------------------
// Baseline-ISA helpers (compile for plain sm_103 — no arch-accelerated feats)
// ---------------------------------------------------------------------------
__device__ __forceinline__ uint32_t smem_u32(const void* p) {
    uint32_t a;
    asm("{ .reg .u64 t; cvta.to.shared.u64 t, %1; cvt.u32.u64 %0, t; }" : "=r"(a) : "l"(p));
    return a;
}
__device__ __forceinline__ float tanh_fast(float v) {
    float r; asm("tanh.approx.f32 %0, %1;" : "=f"(r) : "f"(v)); return r;
}
__device__ __forceinline__ uint32_t cvt_bf16x2(float lo, float hi) {
    uint32_t r;  // packs: low half = lo, high half = hi
    asm("cvt.rn.bf16x2.f32 %0, %1, %2;" : "=r"(r) : "f"(hi), "f"(lo));
    return r;
}
__device__ __forceinline__ void mma_bf16(float* d, const uint32_t* a, uint32_t b0, uint32_t b1) {
    asm volatile(
        "mma.sync.aligned.m16n8k16.row.col.f32.bf16.bf16.f32 "
        "{%0,%1,%2,%3}, {%4,%5,%6,%7}, {%8,%9}, {%0,%1,%2,%3};"
        : "+f"(d[0]), "+f"(d[1]), "+f"(d[2]), "+f"(d[3])
        : "r"(a[0]), "r"(a[1]), "r"(a[2]), "r"(a[3]), "r"(b0), "r"(b1));
}
__device__ __forceinline__ uint2 lds_v2(uint32_t addr) {
    uint2 v;
    asm volatile("ld.shared.v2.b32 {%0, %1}, [%2];" : "=r"(v.x), "=r"(v.y) : "r"(addr));
    return v;
}

// ---------------------------------------------------------------------------
// SMEM: 0: Bfrag(4096)  4096: bz(128)  4224: bh(128)  4352: wl(128)
//       4480: wsum(32)   total 4512
// ---------------------------------------------------------------------------
#define OFF_BZ  4096
#define OFF_BH  4224
#define OFF_WL  4352
#define OFF_WS  4480
#define SMEM_SZ 4512

__global__ __launch_bounds__(256, 3)
void rgcn_kernel(const float* __restrict__ x, float* __restrict__ out) {
    extern __shared__ char smem[];
    const uint32_t sb = smem_u32(smem);
    const int t    = threadIdx.x;
    const int lane = t & 31;
    const int wid  = t >> 5;

    // ---- stage B fragments (4KB) + biases into shared ----
    reinterpret_cast<uint4*>(smem)[t] = reinterpret_cast<const uint4*>(g_Bfrag)[t];
    if (t < 32) {
        reinterpret_cast<float*>(smem + OFF_BZ)[t] = g_bz[t];
        reinterpret_cast<float*>(smem + OFF_BH)[t] = g_bh[t];
        reinterpret_cast<float*>(smem + OFF_WL)[t] = g_wl[t];
    }

    // ---- direct A-fragment LDG (no smem staging, no ldmatrix) ----
    // A frag (row.col m16n8k16): a0 = x[R+gr][gc,gc+1], a1 = x[R+gr+8][gc,gc+1],
    // a2 = x[R+gr][gc+8,gc+9], a3 = x[R+gr+8][gc+8,gc+9]; R = warp base + 16m.
    // lo residual computed in the owning lane: lo = x - bf16(x).
    const int gr = lane >> 2;
    const int gc2 = lane & 3;                       // float2 col index (cols 2gc2,2gc2+1)
    const int mbase = (blockIdx.x << 8) + (wid << 5);
    const float2* xf = reinterpret_cast<const float2*>(x);

    uint32_t Ah[2][4], Al[2][4];
#pragma unroll
    for (int m = 0; m < 2; m++) {
        const size_t r0 = (size_t)(mbase + (m << 4) + gr) << 3;   // row*8 float2s
        float2 fA = xf[r0 + gc2];
        float2 fB = xf[r0 + gc2 + 4];
        float2 fC = xf[r0 + 64 + gc2];          // row +8
        float2 fD = xf[r0 + 64 + gc2 + 4];
        uint32_t h;
        h = cvt_bf16x2(fA.x, fA.y); Ah[m][0] = h;
        Al[m][0] = cvt_bf16x2(fA.x - __uint_as_float(h << 16),
                              fA.y - __uint_as_float(h & 0xffff0000u));
        h = cvt_bf16x2(fC.x, fC.y); Ah[m][1] = h;
        Al[m][1] = cvt_bf16x2(fC.x - __uint_as_float(h << 16),
                              fC.y - __uint_as_float(h & 0xffff0000u));
        h = cvt_bf16x2(fB.x, fB.y); Ah[m][2] = h;
        Al[m][2] = cvt_bf16x2(fB.x - __uint_as_float(h << 16),
                              fB.y - __uint_as_float(h & 0xffff0000u));
        h = cvt_bf16x2(fD.x, fD.y); Ah[m][3] = h;
        Al[m][3] = cvt_bf16x2(fD.x - __uint_as_float(h << 16),
                              fD.y - __uint_as_float(h & 0xffff0000u));
    }
    __syncthreads();

    const float* sbz = reinterpret_cast<const float*>(smem + OFF_BZ);
    const float* sbh = reinterpret_cast<const float*>(smem + OFF_BH);
    const float* swl = reinterpret_cast<const float*>(smem + OFF_WL);
    const uint32_t bfb = sb + lane * 8;             // per-lane B-frag base
    const int c0 = gc2 << 1;

    float s = 0.f;
#pragma unroll
    for (int p = 0; p < 4; p++) {
        // B fragments: (v,nt) at offset ((v*8+nt)*32)*8 from per-lane base
        uint2 Bzh = lds_v2(bfb + (p)      * 256);
        uint2 Bth = lds_v2(bfb + (p + 4)  * 256);
        uint2 Bzl = lds_v2(bfb + (p + 8)  * 256);
        uint2 Btl = lds_v2(bfb + (p + 12) * 256);
        float2 bz2 = *reinterpret_cast<const float2*>(sbz + 8 * p + c0);
        float2 bh2 = *reinterpret_cast<const float2*>(sbh + 8 * p + c0);
        float2 wl2 = *reinterpret_cast<const float2*>(swl + 8 * p + c0);

#pragma unroll
        for (int m = 0; m < 2; m++) {
            float Dz[4] = {0.f, 0.f, 0.f, 0.f};
            float Dt[4] = {0.f, 0.f, 0.f, 0.f};
            mma_bf16(Dz, Ah[m], Bzh.x, Bzh.y);
            mma_bf16(Dt, Ah[m], Bth.x, Bth.y);
            mma_bf16(Dz, Al[m], Bzh.x, Bzh.y);
            mma_bf16(Dt, Al[m], Bth.x, Bth.y);
            mma_bf16(Dz, Ah[m], Bzl.x, Bzl.y);
            mma_bf16(Dt, Ah[m], Btl.x, Btl.y);

#pragma unroll
            for (int i = 0; i < 4; i++) {
                float zb = (i & 1) ? bz2.y : bz2.x;
                float hb = (i & 1) ? bh2.y : bh2.x;
                float wv = (i & 1) ? wl2.y : wl2.x;
                float z  = Dz[i] + zb;                       // already pre-halved
                float tt = Dt[i] + hb;
                float e = fmaf(-0.5f, tanh_fast(z), 0.5f);   // 1 - sigmoid
                float h = tanh_fast(tt);
                s = fmaf(fmaxf(e * h, 0.f), wv, s);
            }
        }
    }

    // ---- block reduction over the graph's 256 nodes ----
#pragma unroll
    for (int off = 16; off > 0; off >>= 1)
        s += __shfl_xor_sync(0xffffffffu, s, off);
    float* wsum = reinterpret_cast<float*>(smem + OFF_WS);
    if (lane == 0) wsum[wid] = s;
    __syncthreads();
    if (t == 0) {
        float tot = ((wsum[0] + wsum[1]) + (wsum[2] + wsum[3])) +
                    ((wsum[4] + wsum[5]) + (wsum[6] + wsum[7]));
        out[blockIdx.x] = tot * (1.0f / 256.0f) + g_bl;
    }
}

// ---------------------------------------------------------------------------
// Inputs: 0:x 1:edge_index 2:edge_weight 3:batch 4:W_z 5:b_z 6:W_r 7:b_r
//         8:W_h 9:b_h 10:W_lin 11:b_lin
// edge_index/edge_weight/batch/W_r/b_r mathematically unused (K=1, h0=0,
// batch = repeat(arange(4096),256)).
// ---------------------------------------------------------------------------
extern "C" void kernel_launch(void* const* d_in, const int* in_sizes, int n_in,
                              void* d_out, int out_size) {
    (void)in_sizes; (void)n_in; (void)out_size;
    const float* x  = (const float*)d_in[0];
    const float* Wz = (const float*)d_in[4];
    const float* bz = (const float*)d_in[5];
    const float* Wh = (const float*)d_in[8];
    const float* bh = (const float*)d_in[9];
    const float* wl = (const float*)d_in[10];
    const float* bl = (const float*)d_in[11];
    float* out = (float*)d_out;

    prep_kernel<<<1, 1024>>>(Wz, bz, Wh, bh, wl, bl);
    rgcn_kernel<<<N_GRAPHS, 256, SMEM_SZ>>>(x, out);
}